// round 6
// baseline (speedup 1.0000x reference)
#include <cuda_runtime.h>
#include <cuda_bf16.h>

#define EDIM 512
#define TM 128          // tokens per CTA (2 halves x 64)
#define TMH 64          // tokens per half
#define TQ 128          // codes per chunk (per half)
#define KC 64           // k per slab
#define NKC (EDIM/KC)   // 8
#define STG 3           // cp.async ring stages
#define THREADS 512
#define MARGIN 0.015f
#define CAPG 64
#define MAX_N 16384
#define MAX_Q 8192
#define CONVB 512

// ---- device scratch ----
__device__ float g_xsq[MAX_N];
__device__ float g_wsq[MAX_Q];
__device__ __nv_bfloat16 g_xbf[(size_t)MAX_N * EDIM];
__device__ __nv_bfloat16 g_wbf[(size_t)MAX_Q * EDIM];
__device__ int g_nc[MAX_N];
__device__ int g_cand[(size_t)MAX_N * CAPG];

// ---- smem layout ----
#define OF_X    0                          // 128 rows x 1024B = 131072 (both halves)
#define OF_W    131072                     // 2 halves x 3 stages x 16384
#define WSLAB   16384
#define OF_WSQ  (OF_W + 2*STG*WSLAB)       // 229376; 2 x 128 floats
#define OF_RUN  (OF_WSQ + 1024)            // 230400; 2 x 64 u32
#define OF_IBUF (OF_RUN + 512)             // 230912; 128 ints
#define SMEM_TOTAL (OF_IBUF + 512)         // 231424 (< 227KB cap)

// ======================= helpers =======================
__device__ __forceinline__ unsigned smem_u32(const void* p) {
    unsigned a;
    asm("{ .reg .u64 t; cvta.to.shared.u64 t, %1; cvt.u32.u64 %0, t; }"
        : "=r"(a) : "l"(p));
    return a;
}
__device__ __forceinline__ unsigned fkey(float f) {
    unsigned u = __float_as_uint(f);
    return (u & 0x80000000u) ? ~u : (u | 0x80000000u);
}
__device__ __forceinline__ float funkey(unsigned k) {
    unsigned u = (k & 0x80000000u) ? (k & 0x7FFFFFFFu) : ~k;
    return __uint_as_float(u);
}
#define BARH(h) asm volatile("bar.sync %0, %1;" :: "r"(1 + (h)), "r"(256) : "memory")
#define CP_ASYNC16(dst, src) \
    asm volatile("cp.async.cg.shared.global [%0], [%1], 16;" \
                 :: "r"(dst), "l"(src) : "memory")
#define CP_COMMIT() asm volatile("cp.async.commit_group;" ::: "memory")
#define LDSM_X4(a0,a1,a2,a3,addr) \
    asm volatile("ldmatrix.sync.aligned.m8n8.x4.shared.b16 {%0,%1,%2,%3}, [%4];" \
        : "=r"(a0),"=r"(a1),"=r"(a2),"=r"(a3) : "r"(addr))
#define MMA16816(c, a, b) \
    asm volatile("mma.sync.aligned.m16n8k16.row.col.f32.bf16.bf16.f32 " \
        "{%0,%1,%2,%3}, {%4,%5,%6,%7}, {%8,%9}, {%0,%1,%2,%3};" \
        : "+f"((c)[0]),"+f"((c)[1]),"+f"((c)[2]),"+f"((c)[3]) \
        : "r"((a)[0]),"r"((a)[1]),"r"((a)[2]),"r"((a)[3]), \
          "r"((b)[0]),"r"((b)[1]))

// ======================= prep kernel =======================
__global__ void prep_kernel(const float* __restrict__ x,
                            const float* __restrict__ w, int N, int Q) {
    if (blockIdx.x < CONVB) {
        size_t i = (size_t)blockIdx.x * blockDim.x + threadIdx.x;
        size_t stride = (size_t)CONVB * blockDim.x;
        size_t nx = (size_t)N * EDIM, nw = (size_t)Q * EDIM;
        for (size_t k = i; k < nx; k += stride) g_xbf[k] = __float2bfloat16(x[k]);
        for (size_t k = i; k < nw; k += stride) g_wbf[k] = __float2bfloat16(w[k]);
        for (size_t k = i; k < (size_t)N; k += stride) g_nc[k] = 0;
    } else {
        int r = (blockIdx.x - CONVB) * blockDim.x + threadIdx.x;
        const float* p; float* dst;
        if (r < N) { p = x + (size_t)r * EDIM; dst = &g_xsq[r]; }
        else if (r < N + Q) { p = w + (size_t)(r - N) * EDIM; dst = &g_wsq[r - N]; }
        else return;
        const float4* p4 = (const float4*)p;
        float acc = 0.0f;   // sequential rounding order (bitwise-validated R1)
        for (int e = 0; e < EDIM / 4; ++e) {
            float4 v = __ldg(p4 + e);
            acc = __fadd_rn(acc, __fmul_rn(v.x, v.x));
            acc = __fadd_rn(acc, __fmul_rn(v.y, v.y));
            acc = __fadd_rn(acc, __fmul_rn(v.z, v.z));
            acc = __fadd_rn(acc, __fmul_rn(v.w, v.w));
        }
        *dst = acc;
    }
}

// stage one 16KB W slab (TQ rows x KC k) for half h, stage st
__device__ __forceinline__ void stage_w(unsigned sb, int h, int st, int qc, int kc,
                                        int tidh) {
    const __nv_bfloat16* src = g_wbf + (size_t)qc * EDIM + kc * KC;
    unsigned dbase = sb + OF_W + (h * STG + st) * WSLAB;
    #pragma unroll
    for (int rep = 0; rep < 4; ++rep) {
        int v = tidh + rep * 256;
        int row = v >> 3, u = v & 7;
        unsigned dst = dbase + row * 128 + ((u * 16) ^ ((row & 7) << 4));
        CP_ASYNC16(dst, src + (size_t)row * EDIM + u * 8);
    }
    CP_COMMIT();
}

// ======================= main kernel =======================
// 512 threads = 2 independent halves of 256 (8 warps: 2m x 4n, tile 32x32)
__global__ void __launch_bounds__(THREADS, 1)
vq_mma_kernel(const float* __restrict__ x, const float* __restrict__ w,
              float* __restrict__ out, int N, int Q, long long out_elems) {
    extern __shared__ char S[];
    const unsigned sb = smem_u32(S);

    const int tid  = threadIdx.x;
    const int lane = tid & 31;
    const int h    = tid >> 8;           // half 0/1
    const int tidh = tid & 255;
    const int widh = tidh >> 5;          // 0..7
    const int wm   = widh >> 2;          // 0..1 (32 tokens)
    const int wn   = widh & 3;           // 0..3 (32 codes)
    const int t0   = blockIdx.x * TM;
    const int th0  = t0 + h * TMH;       // first token of this half

    unsigned* runk = (unsigned*)(S + OF_RUN) + h * TMH;
    float*    wsqs = (float*)(S + OF_WSQ) + h * TQ;

    if (tid < TM) ((unsigned*)(S + OF_RUN))[tid] = 0xFFFFFFFFu;

    // resident X tile: 128 rows x 1024B, swizzled (half h owns rows h*64..)
    const __nv_bfloat16* xb = g_xbf + (size_t)t0 * EDIM;
    for (int v = tid; v < TM * 64; v += THREADS) {
        int row = v >> 6, u = v & 63;
        uint4 val = *(const uint4*)(xb + (size_t)row * EDIM + u * 8);
        *(uint4*)(S + OF_X + row * 1024 + ((u * 16) ^ ((row & 7) << 4))) = val;
    }
    __syncthreads();

    const unsigned xrowbase = sb + OF_X + (h * TMH + wm * 32) * 1024;

    for (int qc = 0; qc < Q; qc += TQ) {
        if (tidh < TQ) wsqs[tidh] = g_wsq[qc + tidh];

        // prologue: stages 0,1
        stage_w(sb, h, 0, qc, 0, tidh);
        stage_w(sb, h, 1, qc, 1, tidh);

        float acc[2][4][4];
        #pragma unroll
        for (int i = 0; i < 2; ++i)
            #pragma unroll
            for (int j = 0; j < 4; ++j)
                #pragma unroll
                for (int k = 0; k < 4; ++k) acc[i][j][k] = 0.0f;

        #pragma unroll 1
        for (int kc = 0; kc < NKC; ++kc) {
            if (kc < NKC - 1) {
                asm volatile("cp.async.wait_group 1;" ::: "memory");
            } else {
                asm volatile("cp.async.wait_group 0;" ::: "memory");
            }
            BARH(h);
            if (kc + 2 < NKC) stage_w(sb, h, (kc + 2) % STG, qc, kc + 2, tidh);

            const unsigned wbase = sb + OF_W + (h * STG + kc % STG) * WSLAB;
            #pragma unroll
            for (int ks = 0; ks < 4; ++ks) {
                unsigned a[2][4], b[4][2];
                #pragma unroll
                for (int mt = 0; mt < 2; ++mt) {
                    int row = wm * 32 + mt * 16 + (lane & 15);   // local in half
                    int u = kc * 8 + ks * 2 + (lane >> 4);
                    unsigned ad = sb + OF_X + (h * TMH + row) * 1024 +
                                  ((u * 16) ^ ((row & 7) << 4));
                    LDSM_X4(a[mt][0], a[mt][1], a[mt][2], a[mt][3], ad);
                }
                #pragma unroll
                for (int ntp = 0; ntp < 2; ++ntp) {
                    int mat = lane >> 3;
                    int row = wn * 32 + (ntp * 2 + (mat >> 1)) * 8 + (lane & 7);
                    int u = ks * 2 + (mat & 1);
                    unsigned bd = wbase + row * 128 + ((u * 16) ^ ((row & 7) << 4));
                    LDSM_X4(b[ntp * 2][0], b[ntp * 2][1],
                            b[ntp * 2 + 1][0], b[ntp * 2 + 1][1], bd);
                }
                #pragma unroll
                for (int mt = 0; mt < 2; ++mt)
                    #pragma unroll
                    for (int nt = 0; nt < 4; ++nt)
                        MMA16816(acc[mt][nt], a[mt], b[nt]);
            }
        }

        // ---- epilogue: s = wsq - 2*dot; two-phase min then candidates ----
        float wsv[4][2];
        const int cbase = wn * 32 + 2 * (lane & 3);
        #pragma unroll
        for (int nt = 0; nt < 4; ++nt) {
            wsv[nt][0] = wsqs[cbase + nt * 8];
            wsv[nt][1] = wsqs[cbase + nt * 8 + 1];
        }
        #pragma unroll
        for (int mt = 0; mt < 2; ++mt) {
            float mlo = 3.4e38f, mhi = 3.4e38f;
            #pragma unroll
            for (int nt = 0; nt < 4; ++nt) {
                acc[mt][nt][0] = __fmaf_rn(-2.0f, acc[mt][nt][0], wsv[nt][0]);
                acc[mt][nt][1] = __fmaf_rn(-2.0f, acc[mt][nt][1], wsv[nt][1]);
                acc[mt][nt][2] = __fmaf_rn(-2.0f, acc[mt][nt][2], wsv[nt][0]);
                acc[mt][nt][3] = __fmaf_rn(-2.0f, acc[mt][nt][3], wsv[nt][1]);
                mlo = fminf(mlo, fminf(acc[mt][nt][0], acc[mt][nt][1]));
                mhi = fminf(mhi, fminf(acc[mt][nt][2], acc[mt][nt][3]));
            }
            int rlo = wm * 32 + mt * 16 + (lane >> 2);
            atomicMin(&runk[rlo], fkey(mlo));
            atomicMin(&runk[rlo + 8], fkey(mhi));
        }
        BARH(h);
        #pragma unroll
        for (int mt = 0; mt < 2; ++mt) {
            int rlo = wm * 32 + mt * 16 + (lane >> 2);
            float thrlo = funkey(runk[rlo]) + MARGIN;
            float thrhi = funkey(runk[rlo + 8]) + MARGIN;
            int tlo = th0 + rlo, thi = tlo + 8;
            #pragma unroll
            for (int nt = 0; nt < 4; ++nt) {
                int c0 = qc + cbase + nt * 8;
                if (acc[mt][nt][0] < thrlo) {
                    int p = atomicAdd(&g_nc[tlo], 1);
                    if (p < CAPG) g_cand[(size_t)tlo * CAPG + p] = c0;
                }
                if (acc[mt][nt][1] < thrlo) {
                    int p = atomicAdd(&g_nc[tlo], 1);
                    if (p < CAPG) g_cand[(size_t)tlo * CAPG + p] = c0 + 1;
                }
                if (acc[mt][nt][2] < thrhi) {
                    int p = atomicAdd(&g_nc[thi], 1);
                    if (p < CAPG) g_cand[(size_t)thi * CAPG + p] = c0;
                }
                if (acc[mt][nt][3] < thrhi) {
                    int p = atomicAdd(&g_nc[thi], 1);
                    if (p < CAPG) g_cand[(size_t)thi * CAPG + p] = c0 + 1;
                }
            }
        }
        BARH(h);   // all phase2 done before wsqs/W-buf overwrite next chunk
    }
    __syncthreads();   // converge halves

    // ---- exact rescore (validated reference-rounding replication) ----
    int* ibuf = (int*)(S + OF_IBUF);
    if (tid < TM) {
        const int t = t0 + tid;
        const float xsq = g_xsq[t];
        const float* xr = x + (size_t)t * EDIM;
        float bestd = 3.4e38f;
        int bestq = 0x7FFFFFFF;
        int nc = g_nc[t];
        if (nc <= CAPG) {
            for (int i = 0; i < nc; ++i) {
                int q = g_cand[(size_t)t * CAPG + i];
                const float* wr = w + (size_t)q * EDIM;
                float dot = 0.0f;
                for (int e = 0; e < EDIM; ++e) dot = __fmaf_rn(xr[e], wr[e], dot);
                float d = __fadd_rn(__fsub_rn(xsq, 2.0f * dot), g_wsq[q]);
                if (d < bestd || (d == bestd && q < bestq)) { bestd = d; bestq = q; }
            }
        } else {   // overflow fallback: exact full scan
            for (int q = 0; q < Q; ++q) {
                const float* wr = w + (size_t)q * EDIM;
                float dot = 0.0f;
                for (int e = 0; e < EDIM; ++e) dot = __fmaf_rn(xr[e], wr[e], dot);
                float d = __fadd_rn(__fsub_rn(xsq, 2.0f * dot), g_wsq[q]);
                if (d < bestd) { bestd = d; bestq = q; }
            }
        }
        ibuf[tid] = bestq;
    }
    __syncthreads();

    // ---- coalesced gather of codebook rows + idx tail ----
    const float4* w4 = (const float4*)w;
    float4* o4 = (float4*)out;
    for (int u = tid; u < TM * (EDIM / 4); u += THREADS) {
        int row = u >> 7, e4 = u & 127;
        o4[(size_t)(t0 + row) * (EDIM / 4) + e4] = w4[(size_t)ibuf[row] * (EDIM / 4) + e4];
    }
    long long NE = (long long)N * EDIM;
    if (out_elems >= NE + N && tid < TM) out[NE + t0 + tid] = (float)ibuf[tid];
}

// ======================= launch =======================
extern "C" void kernel_launch(void* const* d_in, const int* in_sizes, int n_in,
                              void* d_out, int out_size) {
    const float* x = (const float*)d_in[0];
    const float* w = (const float*)d_in[1];
    float* out = (float*)d_out;

    int N = in_sizes[0] / EDIM;   // 16384
    int Q = in_sizes[1] / EDIM;   // 8192
    if (N > MAX_N) N = MAX_N;
    if (Q > MAX_Q) Q = MAX_Q;

    cudaFuncSetAttribute(vq_mma_kernel,
                         cudaFuncAttributeMaxDynamicSharedMemorySize, SMEM_TOTAL);

    int rowblocks = (N + Q + 255) / 256;
    prep_kernel<<<CONVB + rowblocks, 256>>>(x, w, N, Q);
    vq_mma_kernel<<<N / TM, THREADS, SMEM_TOTAL>>>(x, w, out, N, Q,
                                                   (long long)out_size);
}

// round 7
// speedup vs baseline: 1.8232x; 1.8232x over previous
#include <cuda_runtime.h>
#include <cuda_bf16.h>

#define EDIM 512
#define TM 128          // tokens per CTA (2 halves x 64)
#define TMH 64
#define TQ 256          // codes per chunk (per half)
#define KC 32           // k per slab
#define NKC (EDIM/KC)   // 16
#define STG 3
#define THREADS 512
#define MARGIN 0.015f
#define CAPG 64
#define MAX_N 16384
#define MAX_Q 8192
#define CONVB 512

// ---- device scratch ----
__device__ float g_xsq[MAX_N];
__device__ float g_wsq[MAX_Q];
__device__ __nv_bfloat16 g_xbf[(size_t)MAX_N * EDIM];
__device__ __nv_bfloat16 g_wbf[(size_t)MAX_Q * EDIM];
__device__ int g_nc[MAX_N];
__device__ int g_cand[(size_t)MAX_N * CAPG];

// ---- smem layout ----
#define OF_X    0                      // 128 rows x 1024B = 131072
#define OF_W    131072                 // 2 halves x 3 stages x 16384 = 98304
#define WSLAB   16384
#define OF_WSQ  (OF_W + 2*STG*WSLAB)   // 229376 ; 2 x 256 floats = 2048
#define OF_RUN  (OF_WSQ + 2048)        // 231424 ; 2 x 64 u32 = 512
#define OF_IBUF (OF_RUN + 512)         // 231936 ; 128 ints = 512
#define SMEM_TOTAL (OF_IBUF + 512)     // 232448 == 227KB cap
// rescore scratch reuses the dead W ring: bd floats @ OF_W, bq ints @ OF_W+2048

// ======================= helpers =======================
__device__ __forceinline__ unsigned smem_u32(const void* p) {
    unsigned a;
    asm("{ .reg .u64 t; cvta.to.shared.u64 t, %1; cvt.u32.u64 %0, t; }"
        : "=r"(a) : "l"(p));
    return a;
}
__device__ __forceinline__ unsigned fkey(float f) {
    unsigned u = __float_as_uint(f);
    return (u & 0x80000000u) ? ~u : (u | 0x80000000u);
}
__device__ __forceinline__ float funkey(unsigned k) {
    unsigned u = (k & 0x80000000u) ? (k & 0x7FFFFFFFu) : ~k;
    return __uint_as_float(u);
}
#define BARH(h) asm volatile("bar.sync %0, %1;" :: "r"(1 + (h)), "r"(256) : "memory")
#define CP_ASYNC16(dst, src) \
    asm volatile("cp.async.cg.shared.global [%0], [%1], 16;" \
                 :: "r"(dst), "l"(src) : "memory")
#define CP_COMMIT() asm volatile("cp.async.commit_group;" ::: "memory")
#define LDSM_X4(a0,a1,a2,a3,addr) \
    asm volatile("ldmatrix.sync.aligned.m8n8.x4.shared.b16 {%0,%1,%2,%3}, [%4];" \
        : "=r"(a0),"=r"(a1),"=r"(a2),"=r"(a3) : "r"(addr))
#define MMA16816(c, a, b) \
    asm volatile("mma.sync.aligned.m16n8k16.row.col.f32.bf16.bf16.f32 " \
        "{%0,%1,%2,%3}, {%4,%5,%6,%7}, {%8,%9}, {%0,%1,%2,%3};" \
        : "+f"((c)[0]),"+f"((c)[1]),"+f"((c)[2]),"+f"((c)[3]) \
        : "r"((a)[0]),"r"((a)[1]),"r"((a)[2]),"r"((a)[3]), \
          "r"((b)[0]),"r"((b)[1]))

// ======================= prep kernel =======================
__global__ void prep_kernel(const float* __restrict__ x,
                            const float* __restrict__ w, int N, int Q) {
    if (blockIdx.x < CONVB) {
        size_t i = (size_t)blockIdx.x * blockDim.x + threadIdx.x;
        size_t stride = (size_t)CONVB * blockDim.x;
        size_t nx = (size_t)N * EDIM, nw = (size_t)Q * EDIM;
        for (size_t k = i; k < nx; k += stride) g_xbf[k] = __float2bfloat16(x[k]);
        for (size_t k = i; k < nw; k += stride) g_wbf[k] = __float2bfloat16(w[k]);
        for (size_t k = i; k < (size_t)N; k += stride) g_nc[k] = 0;
    } else {
        int r = (blockIdx.x - CONVB) * blockDim.x + threadIdx.x;
        const float* p; float* dst;
        if (r < N) { p = x + (size_t)r * EDIM; dst = &g_xsq[r]; }
        else if (r < N + Q) { p = w + (size_t)(r - N) * EDIM; dst = &g_wsq[r - N]; }
        else return;
        const float4* p4 = (const float4*)p;
        float acc = 0.0f;   // sequential rounding order (bitwise-validated R1)
        for (int e = 0; e < EDIM / 4; ++e) {
            float4 v = __ldg(p4 + e);
            acc = __fadd_rn(acc, __fmul_rn(v.x, v.x));
            acc = __fadd_rn(acc, __fmul_rn(v.y, v.y));
            acc = __fadd_rn(acc, __fmul_rn(v.z, v.z));
            acc = __fadd_rn(acc, __fmul_rn(v.w, v.w));
        }
        *dst = acc;
    }
}

// stage one 16KB W slab (TQ=256 rows x KC=32 k) for half h, stage st
// row stride 64B; swizzle: 16B unit u' = u ^ ((row>>1)&3)  -> conflict-free ldmatrix
__device__ __forceinline__ void stage_w(unsigned sb, int h, int st, int qc, int kc,
                                        int tidh) {
    const __nv_bfloat16* src = g_wbf + (size_t)qc * EDIM + kc * KC;
    unsigned dbase = sb + OF_W + (h * STG + st) * WSLAB;
    #pragma unroll
    for (int rep = 0; rep < 4; ++rep) {
        int v = tidh + rep * 256;
        int row = v >> 2, u = v & 3;
        unsigned dst = dbase + row * 64 + ((u ^ ((row >> 1) & 3)) * 16);
        CP_ASYNC16(dst, src + (size_t)row * EDIM + u * 8);
    }
    CP_COMMIT();
}

// ======================= main kernel =======================
// 512 threads = 2 fully independent halves of 256 (8 warps: 2m x 4n, tile 32x64)
__global__ void __launch_bounds__(THREADS, 1)
vq_mma_kernel(const float* __restrict__ x, const float* __restrict__ w,
              float* __restrict__ out, int N, int Q, long long out_elems) {
    extern __shared__ char S[];
    const unsigned sb = smem_u32(S);

    const int tid  = threadIdx.x;
    const int lane = tid & 31;
    const int h    = tid >> 8;
    const int tidh = tid & 255;
    const int widh = tidh >> 5;
    const int wm   = widh >> 2;          // 0..1 (32 tokens)
    const int wn   = widh & 3;           // 0..3 (64 codes)
    const int t0   = blockIdx.x * TM;
    const int th0  = t0 + h * TMH;

    unsigned* runk = (unsigned*)(S + OF_RUN) + h * TMH;
    float*    wsqs = (float*)(S + OF_WSQ) + h * TQ;

    if (tidh < TMH) runk[tidh] = 0xFFFFFFFFu;

    // resident X rows for this half: h*64 .. h*64+63 (1024B rows, XOR swizzle)
    const __nv_bfloat16* xb = g_xbf + (size_t)t0 * EDIM;
    for (int v = tidh; v < TMH * 64; v += 256) {
        int rl = v >> 6, u = v & 63;
        int row = h * TMH + rl;
        uint4 val = *(const uint4*)(xb + (size_t)row * EDIM + u * 8);
        *(uint4*)(S + OF_X + row * 1024 + ((u * 16) ^ ((row & 7) << 4))) = val;
    }
    BARH(h);

    for (int qc = 0; qc < Q; qc += TQ) {
        wsqs[tidh] = g_wsq[qc + tidh];
        stage_w(sb, h, 0, qc, 0, tidh);
        stage_w(sb, h, 1, qc, 1, tidh);

        float acc[2][8][4];
        #pragma unroll
        for (int i = 0; i < 2; ++i)
            #pragma unroll
            for (int j = 0; j < 8; ++j)
                #pragma unroll
                for (int k = 0; k < 4; ++k) acc[i][j][k] = 0.0f;

        #pragma unroll 1
        for (int kc = 0; kc < NKC; ++kc) {
            if (kc < NKC - 1) {
                asm volatile("cp.async.wait_group 1;" ::: "memory");
            } else {
                asm volatile("cp.async.wait_group 0;" ::: "memory");
            }
            BARH(h);
            if (kc + 2 < NKC) stage_w(sb, h, (kc + 2) % STG, qc, kc + 2, tidh);

            const unsigned wbase = sb + OF_W + (h * STG + kc % STG) * WSLAB;
            #pragma unroll
            for (int ks = 0; ks < 2; ++ks) {
                unsigned a[2][4], b[8][2];
                #pragma unroll
                for (int mt = 0; mt < 2; ++mt) {
                    int row = h * TMH + wm * 32 + mt * 16 + (lane & 15);
                    int u = (kc * 2 + ks) * 2 + (lane >> 4);
                    unsigned ad = sb + OF_X + row * 1024 +
                                  ((u * 16) ^ ((row & 7) << 4));
                    LDSM_X4(a[mt][0], a[mt][1], a[mt][2], a[mt][3], ad);
                }
                #pragma unroll
                for (int ntp = 0; ntp < 4; ++ntp) {
                    int mat = lane >> 3;
                    int row = wn * 64 + (ntp * 2 + (mat >> 1)) * 8 + (lane & 7);
                    int u = ks * 2 + (mat & 1);
                    unsigned bd = wbase + row * 64 + ((u ^ ((row >> 1) & 3)) * 16);
                    LDSM_X4(b[ntp * 2][0], b[ntp * 2][1],
                            b[ntp * 2 + 1][0], b[ntp * 2 + 1][1], bd);
                }
                #pragma unroll
                for (int mt = 0; mt < 2; ++mt)
                    #pragma unroll
                    for (int nt = 0; nt < 8; ++nt)
                        MMA16816(acc[mt][nt], a[mt], b[nt]);
            }
        }

        // ---- epilogue: s = wsq - 2*dot; two-phase min then candidates ----
        float wsv[8][2];
        const int cbase = wn * 64 + 2 * (lane & 3);
        #pragma unroll
        for (int nt = 0; nt < 8; ++nt) {
            wsv[nt][0] = wsqs[cbase + nt * 8];
            wsv[nt][1] = wsqs[cbase + nt * 8 + 1];
        }
        #pragma unroll
        for (int mt = 0; mt < 2; ++mt) {
            float mlo = 3.4e38f, mhi = 3.4e38f;
            #pragma unroll
            for (int nt = 0; nt < 8; ++nt) {
                acc[mt][nt][0] = __fmaf_rn(-2.0f, acc[mt][nt][0], wsv[nt][0]);
                acc[mt][nt][1] = __fmaf_rn(-2.0f, acc[mt][nt][1], wsv[nt][1]);
                acc[mt][nt][2] = __fmaf_rn(-2.0f, acc[mt][nt][2], wsv[nt][0]);
                acc[mt][nt][3] = __fmaf_rn(-2.0f, acc[mt][nt][3], wsv[nt][1]);
                mlo = fminf(mlo, fminf(acc[mt][nt][0], acc[mt][nt][1]));
                mhi = fminf(mhi, fminf(acc[mt][nt][2], acc[mt][nt][3]));
            }
            int rlo = wm * 32 + mt * 16 + (lane >> 2);
            atomicMin(&runk[rlo], fkey(mlo));
            atomicMin(&runk[rlo + 8], fkey(mhi));
        }
        BARH(h);
        #pragma unroll
        for (int mt = 0; mt < 2; ++mt) {
            int rlo = wm * 32 + mt * 16 + (lane >> 2);
            float thrlo = funkey(runk[rlo]) + MARGIN;
            float thrhi = funkey(runk[rlo + 8]) + MARGIN;
            int tlo = th0 + rlo, thi = tlo + 8;
            #pragma unroll
            for (int nt = 0; nt < 8; ++nt) {
                int c0 = qc + cbase + nt * 8;
                if (acc[mt][nt][0] < thrlo) {
                    int p = atomicAdd(&g_nc[tlo], 1);
                    if (p < CAPG) g_cand[(size_t)tlo * CAPG + p] = c0;
                }
                if (acc[mt][nt][1] < thrlo) {
                    int p = atomicAdd(&g_nc[tlo], 1);
                    if (p < CAPG) g_cand[(size_t)tlo * CAPG + p] = c0 + 1;
                }
                if (acc[mt][nt][2] < thrhi) {
                    int p = atomicAdd(&g_nc[thi], 1);
                    if (p < CAPG) g_cand[(size_t)thi * CAPG + p] = c0;
                }
                if (acc[mt][nt][3] < thrhi) {
                    int p = atomicAdd(&g_nc[thi], 1);
                    if (p < CAPG) g_cand[(size_t)thi * CAPG + p] = c0 + 1;
                }
            }
        }
        BARH(h);   // phase2 done before wsqs/ring overwrite next chunk
    }
    BARH(h);       // all candidate writes of this half visible

    // ---- exact rescore: 4 threads per token, float4 sequential order ----
    // (float4 .x.y.z.w accumulation == scalar ascending-e order, bitwise)
    float* rd = (float*)(S + OF_W);          // ring is dead; reuse as scratch
    int*   rq = (int*)(S + OF_W + 2048);
    {
        const int tl = tidh & 63;            // token within half
        const int j  = tidh >> 6;            // 0..3
        const int t  = th0 + tl;
        const float xsq = g_xsq[t];
        const float4* xr4 = (const float4*)(x + (size_t)t * EDIM);
        float bestd = 3.4e38f;
        int bestq = 0x7FFFFFFF;
        int nc = g_nc[t];
        if (nc <= CAPG) {
            for (int i = j; i < nc; i += 4) {
                int q = g_cand[(size_t)t * CAPG + i];
                const float4* wr4 = (const float4*)(w + (size_t)q * EDIM);
                float dot = 0.0f;
                #pragma unroll 4
                for (int e = 0; e < EDIM / 4; ++e) {
                    float4 xv = xr4[e], wv = __ldg(wr4 + e);
                    dot = __fmaf_rn(xv.x, wv.x, dot);
                    dot = __fmaf_rn(xv.y, wv.y, dot);
                    dot = __fmaf_rn(xv.z, wv.z, dot);
                    dot = __fmaf_rn(xv.w, wv.w, dot);
                }
                float d = __fadd_rn(__fsub_rn(xsq, 2.0f * dot), g_wsq[q]);
                if (d < bestd || (d == bestd && q < bestq)) { bestd = d; bestq = q; }
            }
        } else {   // overflow fallback: exact full scan, split by residue
            for (int q = j; q < Q; q += 4) {
                const float4* wr4 = (const float4*)(w + (size_t)q * EDIM);
                float dot = 0.0f;
                #pragma unroll 4
                for (int e = 0; e < EDIM / 4; ++e) {
                    float4 xv = xr4[e], wv = __ldg(wr4 + e);
                    dot = __fmaf_rn(xv.x, wv.x, dot);
                    dot = __fmaf_rn(xv.y, wv.y, dot);
                    dot = __fmaf_rn(xv.z, wv.z, dot);
                    dot = __fmaf_rn(xv.w, wv.w, dot);
                }
                float d = __fadd_rn(__fsub_rn(xsq, 2.0f * dot), g_wsq[q]);
                if (d < bestd || (d == bestd && q < bestq)) { bestd = d; bestq = q; }
            }
        }
        int slot = (h * TMH + tl) * 4 + j;
        rd[slot] = bestd;
        rq[slot] = bestq;
    }
    BARH(h);

    int* ibuf = (int*)(S + OF_IBUF);
    if (tidh < TMH) {
        int base = (h * TMH + tidh) * 4;
        float bd = rd[base]; int bq = rq[base];
        #pragma unroll
        for (int j = 1; j < 4; ++j) {
            float d = rd[base + j]; int q = rq[base + j];
            if (d < bd || (d == bd && q < bq)) { bd = d; bq = q; }
        }
        ibuf[h * TMH + tidh] = bq;
    }
    BARH(h);

    // ---- coalesced gather of this half's codebook rows + idx tail ----
    const float4* w4 = (const float4*)w;
    float4* o4 = (float4*)out;
    for (int v = tidh; v < TMH * (EDIM / 4); v += 256) {
        int rl = v >> 7, e4 = v & 127;
        int row = h * TMH + rl;
        o4[(size_t)(t0 + row) * (EDIM / 4) + e4] =
            w4[(size_t)ibuf[row] * (EDIM / 4) + e4];
    }
    long long NE = (long long)N * EDIM;
    if (out_elems >= NE + N && tidh < TMH)
        out[NE + th0 + tidh] = (float)ibuf[h * TMH + tidh];
}

// ======================= launch =======================
extern "C" void kernel_launch(void* const* d_in, const int* in_sizes, int n_in,
                              void* d_out, int out_size) {
    const float* x = (const float*)d_in[0];
    const float* w = (const float*)d_in[1];
    float* out = (float*)d_out;

    int N = in_sizes[0] / EDIM;   // 16384
    int Q = in_sizes[1] / EDIM;   // 8192
    if (N > MAX_N) N = MAX_N;
    if (Q > MAX_Q) Q = MAX_Q;

    cudaFuncSetAttribute(vq_mma_kernel,
                         cudaFuncAttributeMaxDynamicSharedMemorySize, SMEM_TOTAL);

    int rowblocks = (N + Q + 255) / 256;
    prep_kernel<<<CONVB + rowblocks, 256>>>(x, w, N, Q);
    vq_mma_kernel<<<N / TM, THREADS, SMEM_TOTAL>>>(x, w, out, N, Q,
                                                   (long long)out_size);
}

// round 9
// speedup vs baseline: 2.0308x; 1.1139x over previous
#include <cuda_runtime.h>
#include <cuda_bf16.h>

#define EDIM 512
#define TMH 64          // tokens per CTA
#define TQ 256          // codes per chunk
#define KC 32           // k per slab
#define NKC (EDIM/KC)   // 16
#define STG 2
#define THREADS 256
#define MARGIN 0.015f
#define CAPG 64
#define MAX_N 16384
#define MAX_Q 8192
#define CONVB 512

// ---- device scratch ----
__device__ float g_xsq[MAX_N];
__device__ float g_wsq[MAX_Q];
__device__ __nv_bfloat16 g_xbf[(size_t)MAX_N * EDIM];
__device__ __nv_bfloat16 g_wbf[(size_t)MAX_Q * EDIM];
__device__ int g_nc[MAX_N];
__device__ int g_cand[(size_t)MAX_N * CAPG];

// ---- smem layout (per CTA, ~99.8KB -> 2 CTAs/SM) ----
#define OF_X    0                      // 64 rows x 1024B = 65536
#define OF_W    65536                  // 2 stages x 16384 = 32768
#define WSLAB   16384
#define OF_WSQ  (OF_W + STG*WSLAB)     // 98304 ; 256 floats
#define OF_RUN  (OF_WSQ + 1024)        // 99328 ; 64 u32
#define OF_IBUF (OF_RUN + 256)         // 99584 ; 64 ints
#define SMEM_TOTAL (OF_IBUF + 256)     // 99840
// rescore scratch reuses dead W ring: rd @ OF_W (1KB), rq @ OF_W+1024 (1KB)

// ======================= helpers =======================
__device__ __forceinline__ unsigned smem_u32(const void* p) {
    unsigned a;
    asm("{ .reg .u64 t; cvta.to.shared.u64 t, %1; cvt.u32.u64 %0, t; }"
        : "=r"(a) : "l"(p));
    return a;
}
__device__ __forceinline__ unsigned fkey(float f) {
    unsigned u = __float_as_uint(f);
    return (u & 0x80000000u) ? ~u : (u | 0x80000000u);
}
__device__ __forceinline__ float funkey(unsigned k) {
    unsigned u = (k & 0x80000000u) ? (k & 0x7FFFFFFFu) : ~k;
    return __uint_as_float(u);
}
#define CP_ASYNC16(dst, src) \
    asm volatile("cp.async.cg.shared.global [%0], [%1], 16;" \
                 :: "r"(dst), "l"(src) : "memory")
#define CP_COMMIT() asm volatile("cp.async.commit_group;" ::: "memory")
#define LDSM_X4(a0,a1,a2,a3,addr) \
    asm volatile("ldmatrix.sync.aligned.m8n8.x4.shared.b16 {%0,%1,%2,%3}, [%4];" \
        : "=r"(a0),"=r"(a1),"=r"(a2),"=r"(a3) : "r"(addr))
#define MMA16816(c, a, b) \
    asm volatile("mma.sync.aligned.m16n8k16.row.col.f32.bf16.bf16.f32 " \
        "{%0,%1,%2,%3}, {%4,%5,%6,%7}, {%8,%9}, {%0,%1,%2,%3};" \
        : "+f"((c)[0]),"+f"((c)[1]),"+f"((c)[2]),"+f"((c)[3]) \
        : "r"((a)[0]),"r"((a)[1]),"r"((a)[2]),"r"((a)[3]), \
          "r"((b)[0]),"r"((b)[1]))

// ======================= prep kernel =======================
__global__ void prep_kernel(const float* __restrict__ x,
                            const float* __restrict__ w, int N, int Q) {
    if (blockIdx.x < CONVB) {
        size_t i = (size_t)blockIdx.x * blockDim.x + threadIdx.x;
        size_t stride = (size_t)CONVB * blockDim.x;
        size_t nx = (size_t)N * EDIM, nw = (size_t)Q * EDIM;
        for (size_t k = i; k < nx; k += stride) g_xbf[k] = __float2bfloat16(x[k]);
        for (size_t k = i; k < nw; k += stride) g_wbf[k] = __float2bfloat16(w[k]);
        for (size_t k = i; k < (size_t)N; k += stride) g_nc[k] = 0;
    } else {
        int r = (blockIdx.x - CONVB) * blockDim.x + threadIdx.x;
        const float* p; float* dst;
        if (r < N) { p = x + (size_t)r * EDIM; dst = &g_xsq[r]; }
        else if (r < N + Q) { p = w + (size_t)(r - N) * EDIM; dst = &g_wsq[r - N]; }
        else return;
        const float4* p4 = (const float4*)p;
        float acc = 0.0f;   // sequential rounding order (bitwise-validated R1)
        for (int e = 0; e < EDIM / 4; ++e) {
            float4 v = __ldg(p4 + e);
            acc = __fadd_rn(acc, __fmul_rn(v.x, v.x));
            acc = __fadd_rn(acc, __fmul_rn(v.y, v.y));
            acc = __fadd_rn(acc, __fmul_rn(v.z, v.z));
            acc = __fadd_rn(acc, __fmul_rn(v.w, v.w));
        }
        *dst = acc;
    }
}

// stage one 16KB W slab (TQ=256 rows x KC=32 k), stage st
__device__ __forceinline__ void stage_w(unsigned sb, int st, int qc, int kc,
                                        int tid) {
    const __nv_bfloat16* src = g_wbf + (size_t)qc * EDIM + kc * KC;
    unsigned dbase = sb + OF_W + st * WSLAB;
    #pragma unroll
    for (int rep = 0; rep < 4; ++rep) {
        int v = tid + rep * 256;
        int row = v >> 2, u = v & 3;
        unsigned dst = dbase + row * 64 + ((u ^ ((row >> 1) & 3)) * 16);
        CP_ASYNC16(dst, src + (size_t)row * EDIM + u * 8);
    }
    CP_COMMIT();
}

// ======================= main kernel =======================
// 256 threads, 8 warps (2m x 4n), warp tile 32 tokens x 64 codes; 2 CTAs/SM
__global__ void __launch_bounds__(THREADS, 2)
vq_mma_kernel(const float* __restrict__ x, const float* __restrict__ w,
              float* __restrict__ out, int N, int Q, long long out_elems) {
    extern __shared__ char S[];
    const unsigned sb = smem_u32(S);

    const int tid  = threadIdx.x;
    const int lane = tid & 31;
    const int wid  = tid >> 5;
    const int wm   = wid >> 2;           // 0..1 (32 tokens)
    const int wn   = wid & 3;            // 0..3 (64 codes)
    const int t0   = blockIdx.x * TMH;

    unsigned* runk = (unsigned*)(S + OF_RUN);
    float*    wsqs = (float*)(S + OF_WSQ);

    if (tid < TMH) runk[tid] = 0xFFFFFFFFu;

    // resident X tile: 64 rows x 1024B, XOR swizzle
    const __nv_bfloat16* xb = g_xbf + (size_t)t0 * EDIM;
    for (int v = tid; v < TMH * 64; v += THREADS) {
        int row = v >> 6, u = v & 63;
        uint4 val = *(const uint4*)(xb + (size_t)row * EDIM + u * 8);
        *(uint4*)(S + OF_X + row * 1024 + ((u * 16) ^ ((row & 7) << 4))) = val;
    }
    __syncthreads();

    for (int qc = 0; qc < Q; qc += TQ) {
        wsqs[tid] = g_wsq[qc + tid];
        stage_w(sb, 0, qc, 0, tid);

        float acc[2][8][4];
        #pragma unroll
        for (int i = 0; i < 2; ++i)
            #pragma unroll
            for (int j = 0; j < 8; ++j)
                #pragma unroll
                for (int k = 0; k < 4; ++k) acc[i][j][k] = 0.0f;

        #pragma unroll 1
        for (int kc = 0; kc < NKC; ++kc) {
            asm volatile("cp.async.wait_group 0;" ::: "memory");
            __syncthreads();
            if (kc + 1 < NKC) stage_w(sb, (kc + 1) & 1, qc, kc + 1, tid);

            const unsigned wbase = sb + OF_W + (kc & 1) * WSLAB;
            #pragma unroll
            for (int ks = 0; ks < 2; ++ks) {
                unsigned a[2][4], b[8][2];
                #pragma unroll
                for (int mt = 0; mt < 2; ++mt) {
                    int row = wm * 32 + mt * 16 + (lane & 15);
                    int u = (kc * 2 + ks) * 2 + (lane >> 4);
                    unsigned ad = sb + OF_X + row * 1024 +
                                  ((u * 16) ^ ((row & 7) << 4));
                    LDSM_X4(a[mt][0], a[mt][1], a[mt][2], a[mt][3], ad);
                }
                #pragma unroll
                for (int ntp = 0; ntp < 4; ++ntp) {
                    int mat = lane >> 3;
                    int row = wn * 64 + (ntp * 2 + (mat >> 1)) * 8 + (lane & 7);
                    int u = ks * 2 + (mat & 1);
                    unsigned bd = wbase + row * 64 + ((u ^ ((row >> 1) & 3)) * 16);
                    LDSM_X4(b[ntp * 2][0], b[ntp * 2][1],
                            b[ntp * 2 + 1][0], b[ntp * 2 + 1][1], bd);
                }
                #pragma unroll
                for (int mt = 0; mt < 2; ++mt)
                    #pragma unroll
                    for (int nt = 0; nt < 8; ++nt)
                        MMA16816(acc[mt][nt], a[mt], b[nt]);
            }
        }

        // ---- epilogue: s = wsq - 2*dot; two-phase min then candidates ----
        float wsv[8][2];
        const int cbase = wn * 64 + 2 * (lane & 3);
        #pragma unroll
        for (int nt = 0; nt < 8; ++nt) {
            wsv[nt][0] = wsqs[cbase + nt * 8];
            wsv[nt][1] = wsqs[cbase + nt * 8 + 1];
        }
        #pragma unroll
        for (int mt = 0; mt < 2; ++mt) {
            float mlo = 3.4e38f, mhi = 3.4e38f;
            #pragma unroll
            for (int nt = 0; nt < 8; ++nt) {
                acc[mt][nt][0] = __fmaf_rn(-2.0f, acc[mt][nt][0], wsv[nt][0]);
                acc[mt][nt][1] = __fmaf_rn(-2.0f, acc[mt][nt][1], wsv[nt][1]);
                acc[mt][nt][2] = __fmaf_rn(-2.0f, acc[mt][nt][2], wsv[nt][0]);
                acc[mt][nt][3] = __fmaf_rn(-2.0f, acc[mt][nt][3], wsv[nt][1]);
                mlo = fminf(mlo, fminf(acc[mt][nt][0], acc[mt][nt][1]));
                mhi = fminf(mhi, fminf(acc[mt][nt][2], acc[mt][nt][3]));
            }
            int rlo = wm * 32 + mt * 16 + (lane >> 2);
            atomicMin(&runk[rlo], fkey(mlo));
            atomicMin(&runk[rlo + 8], fkey(mhi));
        }
        __syncthreads();
        #pragma unroll
        for (int mt = 0; mt < 2; ++mt) {
            int rlo = wm * 32 + mt * 16 + (lane >> 2);
            float thrlo = funkey(runk[rlo]) + MARGIN;
            float thrhi = funkey(runk[rlo + 8]) + MARGIN;
            int tlo = t0 + rlo, thi = tlo + 8;
            #pragma unroll
            for (int nt = 0; nt < 8; ++nt) {
                int c0 = qc + cbase + nt * 8;
                if (acc[mt][nt][0] < thrlo) {
                    int p = atomicAdd(&g_nc[tlo], 1);
                    if (p < CAPG) g_cand[(size_t)tlo * CAPG + p] = c0;
                }
                if (acc[mt][nt][1] < thrlo) {
                    int p = atomicAdd(&g_nc[tlo], 1);
                    if (p < CAPG) g_cand[(size_t)tlo * CAPG + p] = c0 + 1;
                }
                if (acc[mt][nt][2] < thrhi) {
                    int p = atomicAdd(&g_nc[thi], 1);
                    if (p < CAPG) g_cand[(size_t)thi * CAPG + p] = c0;
                }
                if (acc[mt][nt][3] < thrhi) {
                    int p = atomicAdd(&g_nc[thi], 1);
                    if (p < CAPG) g_cand[(size_t)thi * CAPG + p] = c0 + 1;
                }
            }
        }
        __syncthreads();   // phase2 done before wsqs/ring overwrite next chunk
    }

    // ---- exact rescore: 4 threads per token, float4 sequential order ----
    float* rd = (float*)(S + OF_W);          // ring dead; reuse as scratch
    int*   rq = (int*)(S + OF_W + 1024);
    {
        const int tl = tid & 63;
        const int j  = tid >> 6;             // 0..3
        const int t  = t0 + tl;
        const float xsq = g_xsq[t];
        const float4* xr4 = (const float4*)(x + (size_t)t * EDIM);
        float bestd = 3.4e38f;
        int bestq = 0x7FFFFFFF;
        int nc = g_nc[t];
        if (nc <= CAPG) {
            for (int i = j; i < nc; i += 4) {
                int q = g_cand[(size_t)t * CAPG + i];
                const float4* wr4 = (const float4*)(w + (size_t)q * EDIM);
                float dot = 0.0f;
                #pragma unroll 4
                for (int e = 0; e < EDIM / 4; ++e) {
                    float4 xv = xr4[e], wv = __ldg(wr4 + e);
                    dot = __fmaf_rn(xv.x, wv.x, dot);
                    dot = __fmaf_rn(xv.y, wv.y, dot);
                    dot = __fmaf_rn(xv.z, wv.z, dot);
                    dot = __fmaf_rn(xv.w, wv.w, dot);
                }
                float d = __fadd_rn(__fsub_rn(xsq, 2.0f * dot), g_wsq[q]);
                if (d < bestd || (d == bestd && q < bestq)) { bestd = d; bestq = q; }
            }
        } else {   // overflow fallback: exact full scan, split by residue
            for (int q = j; q < Q; q += 4) {
                const float4* wr4 = (const float4*)(w + (size_t)q * EDIM);
                float dot = 0.0f;
                #pragma unroll 4
                for (int e = 0; e < EDIM / 4; ++e) {
                    float4 xv = xr4[e], wv = __ldg(wr4 + e);
                    dot = __fmaf_rn(xv.x, wv.x, dot);
                    dot = __fmaf_rn(xv.y, wv.y, dot);
                    dot = __fmaf_rn(xv.z, wv.z, dot);
                    dot = __fmaf_rn(xv.w, wv.w, dot);
                }
                float d = __fadd_rn(__fsub_rn(xsq, 2.0f * dot), g_wsq[q]);
                if (d < bestd || (d == bestd && q < bestq)) { bestd = d; bestq = q; }
            }
        }
        rd[tl * 4 + j] = bestd;
        rq[tl * 4 + j] = bestq;
    }
    __syncthreads();

    int* ibuf = (int*)(S + OF_IBUF);
    if (tid < TMH) {
        int base = tid * 4;
        float bd = rd[base]; int bq = rq[base];
        #pragma unroll
        for (int j = 1; j < 4; ++j) {
            float d = rd[base + j]; int q = rq[base + j];
            if (d < bd || (d == bd && q < bq)) { bd = d; bq = q; }
        }
        ibuf[tid] = bq;
    }
    __syncthreads();

    // ---- coalesced gather of codebook rows + idx tail ----
    const float4* w4 = (const float4*)w;
    float4* o4 = (float4*)out;
    for (int v = tid; v < TMH * (EDIM / 4); v += THREADS) {
        int row = v >> 7, e4 = v & 127;
        o4[(size_t)(t0 + row) * (EDIM / 4) + e4] =
            w4[(size_t)ibuf[row] * (EDIM / 4) + e4];
    }
    long long NE = (long long)N * EDIM;
    if (out_elems >= NE + N && tid < TMH)
        out[NE + t0 + tid] = (float)ibuf[tid];
}

// ======================= launch =======================
extern "C" void kernel_launch(void* const* d_in, const int* in_sizes, int n_in,
                              void* d_out, int out_size) {
    const float* x = (const float*)d_in[0];
    const float* w = (const float*)d_in[1];
    float* out = (float*)d_out;

    int N = in_sizes[0] / EDIM;   // 16384
    int Q = in_sizes[1] / EDIM;   // 8192
    if (N > MAX_N) N = MAX_N;
    if (Q > MAX_Q) Q = MAX_Q;

    cudaFuncSetAttribute(vq_mma_kernel,
                         cudaFuncAttributeMaxDynamicSharedMemorySize, SMEM_TOTAL);

    int rowblocks = (N + Q + 255) / 256;
    prep_kernel<<<CONVB + rowblocks, 256>>>(x, w, N, Q);
    vq_mma_kernel<<<N / TMH, THREADS, SMEM_TOTAL>>>(x, w, out, N, Q,
                                                    (long long)out_size);
}